// round 11
// baseline (speedup 1.0000x reference)
#include <cuda_runtime.h>
#include <cuda_fp16.h>
#include <math.h>
#include <stdint.h>

// ---------------------------------------------------------------------------
// GCN (3-layer) on 100k nodes / 1.6M edges.  edge_index arrives int32.
// R11: chunked agg->GEMM pipelining across two streams (GEMM_k(chunk0) overlaps
// agg_{k-1}(chunk1)); second h buffer to avoid WAR on gathers; warp-based
// fused agg40+log_softmax.
// ---------------------------------------------------------------------------

#define CH 256
#define OUTCH 40
#define N_NODES_MAX 100000
#define N_EDGES_MAX 1600000
#define SCAN_CHUNK 1024

__device__ __align__(16) __half g_h16[(size_t)N_NODES_MAX * CH];    // hA, 50 MB
__device__ __align__(16) __half g_hB16[(size_t)N_NODES_MAX * CH];   // hB, 50 MB
__device__ __align__(16) __half g_agg16[(size_t)N_NODES_MAX * CH];  // 50 MB
__device__ __align__(16) __half g_w1t[CH * CH];      // [n][k] transposed
__device__ __align__(16) __half g_w2t[CH * CH];
__device__ __align__(16) __half g_w3t[64 * CH];      // padded to 64 rows
__device__ int   g_cnt[N_NODES_MAX];
__device__ int   g_rowptr[N_NODES_MAX + 1];
__device__ int   g_wptr[N_NODES_MAX];
__device__ float g_dinv[N_NODES_MAX];
__device__ __align__(8) int2 g_edge[N_EDGES_MAX];    // (src, norm bits)
__device__ int   g_blocksum[128];
__device__ int   g_blockoff[128];

// ------------------------- CSR build -------------------------

__global__ void zero_cnt_kernel(int n) {
    int i = blockIdx.x * blockDim.x + threadIdx.x;
    if (i < n) g_cnt[i] = 0;
}
__global__ void hist_kernel(const int* __restrict__ ei, int E) {
    int e = blockIdx.x * blockDim.x + threadIdx.x;
    if (e < E) atomicAdd(&g_cnt[ei[E + e]], 1);
}
__global__ void scan_partial_kernel(int n) {
    __shared__ int warpsum[8];
    int base = blockIdx.x * SCAN_CHUNK + threadIdx.x * 4;
    int s = 0;
#pragma unroll
    for (int j = 0; j < 4; j++) { int i = base + j; if (i < n) s += g_cnt[i]; }
    int lane = threadIdx.x & 31, w = threadIdx.x >> 5;
#pragma unroll
    for (int off = 16; off > 0; off >>= 1) s += __shfl_xor_sync(0xFFFFFFFF, s, off);
    if (lane == 0) warpsum[w] = s;
    __syncthreads();
    if (threadIdx.x == 0) {
        int t = 0;
#pragma unroll
        for (int k = 0; k < 8; k++) t += warpsum[k];
        g_blocksum[blockIdx.x] = t;
    }
}
__global__ void scan_blocks_kernel(int nb) {
    int t = threadIdx.x;
    int v = (t < nb) ? g_blocksum[t] : 0;
    int orig = v;
    int lane = t & 31, w = t >> 5;
#pragma unroll
    for (int off = 1; off < 32; off <<= 1) {
        int u = __shfl_up_sync(0xFFFFFFFF, v, off);
        if (lane >= off) v += u;
    }
    __shared__ int ws[4];
    if (lane == 31) ws[w] = v;
    __syncthreads();
    int add = 0;
    for (int k = 0; k < w; k++) add += ws[k];
    if (t < nb) g_blockoff[t] = v + add - orig;
}
__global__ void scan_emit_kernel(int n, int E) {
    __shared__ int warpincl[8];
    int base = blockIdx.x * SCAN_CHUNK + threadIdx.x * 4;
    int c[4];
    int s = 0;
#pragma unroll
    for (int j = 0; j < 4; j++) {
        int i = base + j;
        c[j] = (i < n) ? g_cnt[i] : 0;
        s += c[j];
    }
    int lane = threadIdx.x & 31, w = threadIdx.x >> 5;
    int v = s;
#pragma unroll
    for (int off = 1; off < 32; off <<= 1) {
        int u = __shfl_up_sync(0xFFFFFFFF, v, off);
        if (lane >= off) v += u;
    }
    if (lane == 31) warpincl[w] = v;
    __syncthreads();
    int add = 0;
    for (int k = 0; k < w; k++) add += warpincl[k];
    int run = g_blockoff[blockIdx.x] + add + v - s;
#pragma unroll
    for (int j = 0; j < 4; j++) {
        int i = base + j;
        if (i < n) {
            g_rowptr[i] = run;
            g_wptr[i]   = run;
            g_dinv[i]   = rsqrtf((float)c[j] + 1.0f);
            run += c[j];
        }
    }
    if (blockIdx.x == 0 && threadIdx.x == 0) g_rowptr[n] = E;
}
__global__ void scatter_kernel(const int* __restrict__ ei, int E) {
    int e = blockIdx.x * blockDim.x + threadIdx.x;
    if (e < E) {
        int s = ei[e];
        int d = ei[E + e];
        int pos = atomicAdd(&g_wptr[d], 1);
        float norm = g_dinv[s] * g_dinv[d];
        g_edge[pos] = make_int2(s, __float_as_int(norm));
    }
}

// W1,W2 [k][n] fp32 -> [n][k] fp16; W3 [k][40] -> [64][k] fp16 (zero-padded)
__global__ void convert_w_kernel(const float* __restrict__ W1,
                                 const float* __restrict__ W2,
                                 const float* __restrict__ W3) {
    int n = blockIdx.x;
    int k = threadIdx.x;
    g_w1t[n * 256 + k] = __float2half_rn(__ldg(&W1[k * 256 + n]));
    g_w2t[n * 256 + k] = __float2half_rn(__ldg(&W2[k * 256 + n]));
    if (n < 64)
        g_w3t[n * 256 + k] = __float2half_rn(n < OUTCH ? __ldg(&W3[k * OUTCH + n]) : 0.f);
}

// ------------------- fp16 mma GEMM: C[M,*] = A[M,256] @ W^T -----------------
// BM=128, BN=128 or 64, BK=16. 8 warps 2(M)x4(N); warp tile 64 x BN/4.
// ASEL: 0 = fp32 x (param), 1 = fp16 g_agg16.  WSEL: 0/1/2.  OSEL: 0=hA 1=hB.
// moff: row-block offset (chunked launches).

#define HSTR 24

__device__ __forceinline__ uint32_t smem_cast(const void* p) {
    return (uint32_t)__cvta_generic_to_shared(p);
}

template <int BN, int ASEL, int WSEL, int OSEL>
__global__ __launch_bounds__(256, 2) void gemm_h16_kernel(
    const float* __restrict__ Xf, int M, int NOUT, int OS, int moff)
{
    const __half* Bt = (WSEL == 0) ? g_w1t : (WSEL == 1) ? g_w2t : g_w3t;
    __half* Cout = (OSEL == 0) ? g_h16 : g_hB16;
    constexpr int NTN = BN / 32;

    __shared__ __half As[2][128][HSTR];
    __shared__ __half Bs[2][BN][HSTR];
    constexpr uint32_t ABUF = 128 * HSTR * 2;
    constexpr uint32_t BBUF = BN * HSTR * 2;

    const int tid  = threadIdx.x;
    const int wid  = tid >> 5;
    const int lane = tid & 31;
    const int grp  = lane >> 2;
    const int tig  = lane & 3;
    const int wm   = wid & 1;
    const int wn   = wid >> 1;
    const int m0   = (blockIdx.y + moff) * 128;
    const int n0   = blockIdx.x * BN;

    const int row = tid >> 1;
    const int kc  = tid & 1;

    const int lg   = lane >> 3;
    const int lr   = lane & 7;
    uint32_t aAddrBase = smem_cast(&As[0][wm * 64 + (lg & 1) * 8 + lr][(lg >> 1) * 8]);
    uint32_t bAddrBase = smem_cast(&Bs[0][wn * (BN / 4) + (lg >> 1) * 8 + lr][(lg & 1) * 8]);

    uint4 aH; float4 aF0, aF1; uint4 bG;
    auto loadG = [&](int k0) {
        int gm = m0 + row;
        if (ASEL == 0) {
            if (gm < M) {
                aF0 = __ldg((const float4*)(Xf + (size_t)gm * 256 + k0 + kc * 8));
                aF1 = __ldg((const float4*)(Xf + (size_t)gm * 256 + k0 + kc * 8 + 4));
            } else {
                aF0 = aF1 = make_float4(0.f, 0.f, 0.f, 0.f);
            }
        } else {
            aH = (gm < M) ? __ldg((const uint4*)(g_agg16 + (size_t)gm * 256 + k0 + kc * 8))
                          : make_uint4(0u, 0u, 0u, 0u);
        }
        if (BN == 128 || tid < BN * 2)
            bG = __ldg((const uint4*)(Bt + (size_t)(n0 + row) * 256 + k0 + kc * 8));
    };
    auto storeS = [&](int buf) {
        if (ASEL == 0) {
            uint4 v;
            __half2* p = (__half2*)&v;
            p[0] = __floats2half2_rn(aF0.x, aF0.y);
            p[1] = __floats2half2_rn(aF0.z, aF0.w);
            p[2] = __floats2half2_rn(aF1.x, aF1.y);
            p[3] = __floats2half2_rn(aF1.z, aF1.w);
            *(uint4*)&As[buf][row][kc * 8] = v;
        } else {
            *(uint4*)&As[buf][row][kc * 8] = aH;
        }
        if (BN == 128 || tid < BN * 2)
            *(uint4*)&Bs[buf][row][kc * 8] = bG;
    };

    float acc[4][NTN][4];
#pragma unroll
    for (int mt = 0; mt < 4; mt++)
#pragma unroll
        for (int nt = 0; nt < NTN; nt++)
#pragma unroll
            for (int r = 0; r < 4; r++) acc[mt][nt][r] = 0.0f;

    loadG(0);
    storeS(0);
    __syncthreads();

    const int NT = 256 / 16;
    for (int kt = 0; kt < NT; kt++) {
        const int cur = kt & 1;
        if (kt + 1 < NT) loadG((kt + 1) * 16);

        uint32_t aOff = aAddrBase + cur * ABUF;
        uint32_t bOff = bAddrBase + cur * BBUF;
        uint32_t af[4][4], bf[NTN][2];
#pragma unroll
        for (int mt = 0; mt < 4; mt++) {
            asm volatile(
                "ldmatrix.sync.aligned.m8n8.x4.shared.b16 {%0,%1,%2,%3}, [%4];"
                : "=r"(af[mt][0]), "=r"(af[mt][1]), "=r"(af[mt][2]), "=r"(af[mt][3])
                : "r"(aOff + mt * (16 * HSTR * 2)));
        }
#pragma unroll
        for (int p = 0; p < NTN / 2; p++) {
            asm volatile(
                "ldmatrix.sync.aligned.m8n8.x4.shared.b16 {%0,%1,%2,%3}, [%4];"
                : "=r"(bf[2 * p][0]), "=r"(bf[2 * p][1]),
                  "=r"(bf[2 * p + 1][0]), "=r"(bf[2 * p + 1][1])
                : "r"(bOff + p * (16 * HSTR * 2)));
        }
#pragma unroll
        for (int mt = 0; mt < 4; mt++)
#pragma unroll
            for (int nt = 0; nt < NTN; nt++) {
                asm volatile(
                    "mma.sync.aligned.m16n8k16.row.col.f32.f16.f16.f32 "
                    "{%0,%1,%2,%3}, {%4,%5,%6,%7}, {%8,%9}, {%0,%1,%2,%3};"
                    : "+f"(acc[mt][nt][0]), "+f"(acc[mt][nt][1]),
                      "+f"(acc[mt][nt][2]), "+f"(acc[mt][nt][3])
                    : "r"(af[mt][0]), "r"(af[mt][1]), "r"(af[mt][2]), "r"(af[mt][3]),
                      "r"(bf[nt][0]), "r"(bf[nt][1]));
            }
        if (kt + 1 < NT) storeS(cur ^ 1);
        __syncthreads();
    }

#pragma unroll
    for (int mt = 0; mt < 4; mt++) {
        int gm = m0 + wm * 64 + mt * 16 + grp;
#pragma unroll
        for (int nt = 0; nt < NTN; nt++) {
            int gn = n0 + wn * (BN / 4) + nt * 8 + tig * 2;
            if (gn < NOUT) {
                if (gm < M)
                    *(__half2*)(Cout + (size_t)gm * OS + gn) =
                        __floats2half2_rn(acc[mt][nt][0], acc[mt][nt][1]);
                if (gm + 8 < M)
                    *(__half2*)(Cout + (size_t)(gm + 8) * OS + gn) =
                        __floats2half2_rn(acc[mt][nt][2], acc[mt][nt][3]);
            }
        }
    }
}

// ------------------- Aggregation 256-ch: h gather -> agg16 ------------------
// ISEL: 0 = gather from g_h16 (hA), 1 = g_hB16 (hB). base = first node.
template <int ISEL, bool RELU>
__global__ __launch_bounds__(256) void aggregate256_kernel(
    const float* __restrict__ bias, int base, int n)
{
    const int node = base + blockIdx.x * 8 + (threadIdx.x >> 5);
    const int c8   = threadIdx.x & 31;
    if (node >= n) return;
    const uint4* h = (const uint4*)((ISEL == 0) ? g_h16 : g_hB16);
    const int beg = g_rowptr[node];
    const int end = g_rowptr[node + 1];
    const float di = g_dinv[node];
    const float dii = di * di;

    float acc[8];
    {
        uint4 v = h[(size_t)node * 32 + c8];
        const __half2* hp = (const __half2*)&v;
#pragma unroll
        for (int q = 0; q < 4; q++) {
            float2 f = __half22float2(hp[q]);
            acc[q * 2 + 0] = f.x * dii;
            acc[q * 2 + 1] = f.y * dii;
        }
    }

    int e = beg;
    for (; e + 4 <= end; e += 4) {
        int2 e0 = __ldg(&g_edge[e + 0]);
        int2 e1 = __ldg(&g_edge[e + 1]);
        int2 e2 = __ldg(&g_edge[e + 2]);
        int2 e3 = __ldg(&g_edge[e + 3]);
        uint4 v0 = __ldg(&h[(size_t)e0.x * 32 + c8]);
        uint4 v1 = __ldg(&h[(size_t)e1.x * 32 + c8]);
        uint4 v2 = __ldg(&h[(size_t)e2.x * 32 + c8]);
        uint4 v3 = __ldg(&h[(size_t)e3.x * 32 + c8]);
        float w0 = __int_as_float(e0.y), w1 = __int_as_float(e1.y);
        float w2 = __int_as_float(e2.y), w3 = __int_as_float(e3.y);
        const __half2* p0 = (const __half2*)&v0;
        const __half2* p1 = (const __half2*)&v1;
        const __half2* p2 = (const __half2*)&v2;
        const __half2* p3 = (const __half2*)&v3;
#pragma unroll
        for (int q = 0; q < 4; q++) {
            float2 f0 = __half22float2(p0[q]);
            float2 f1 = __half22float2(p1[q]);
            float2 f2 = __half22float2(p2[q]);
            float2 f3 = __half22float2(p3[q]);
            acc[q * 2 + 0] += w0 * f0.x + w1 * f1.x + w2 * f2.x + w3 * f3.x;
            acc[q * 2 + 1] += w0 * f0.y + w1 * f1.y + w2 * f2.y + w3 * f3.y;
        }
    }
    for (; e < end; e++) {
        int2 ed = __ldg(&g_edge[e]);
        uint4 v0 = __ldg(&h[(size_t)ed.x * 32 + c8]);
        float w0 = __int_as_float(ed.y);
        const __half2* p0 = (const __half2*)&v0;
#pragma unroll
        for (int q = 0; q < 4; q++) {
            float2 f0 = __half22float2(p0[q]);
            acc[q * 2 + 0] += w0 * f0.x;
            acc[q * 2 + 1] += w0 * f0.y;
        }
    }

    float4 b0 = __ldg((const float4*)(bias + c8 * 8));
    float4 b1 = __ldg((const float4*)(bias + c8 * 8 + 4));
    acc[0] += b0.x; acc[1] += b0.y; acc[2] += b0.z; acc[3] += b0.w;
    acc[4] += b1.x; acc[5] += b1.y; acc[6] += b1.z; acc[7] += b1.w;
    if (RELU) {
#pragma unroll
        for (int q = 0; q < 8; q++) acc[q] = fmaxf(acc[q], 0.0f);
    }
    uint4 ov;
    __half2* op = (__half2*)&ov;
    op[0] = __floats2half2_rn(acc[0], acc[1]);
    op[1] = __floats2half2_rn(acc[2], acc[3]);
    op[2] = __floats2half2_rn(acc[4], acc[5]);
    op[3] = __floats2half2_rn(acc[6], acc[7]);
    __stcs((float4*)((uint4*)g_agg16 + (size_t)node * 32 + c8), *(float4*)&ov);
}

// ---------- fused layer-3 aggregation (40 ch) + log_softmax -----------------
// warp per node (4 nodes / 128-thr block); lanes 0..19 own 2 channels each.

__global__ __launch_bounds__(128) void agg40_softmax_kernel(
    const float* __restrict__ bias, float* __restrict__ out, int n)
{
    const int node = blockIdx.x * 4 + (threadIdx.x >> 5);
    const int lane = threadIdx.x & 31;
    if (node >= n) return;
    const uint32_t* h = (const uint32_t*)g_h16;   // 20 u32 per 40-half row
    const bool act = lane < 20;

    const int beg = g_rowptr[node];
    const int end = g_rowptr[node + 1];
    const float di = g_dinv[node];
    const float dii = di * di;

    float2 acc = make_float2(0.f, 0.f);
    if (act) {
        uint32_t sv = __ldg(&h[(size_t)node * 20 + lane]);
        float2 f = __half22float2(*(const __half2*)&sv);
        acc.x = f.x * dii;
        acc.y = f.y * dii;
    }
    int e = beg;
    for (; e + 2 <= end; e += 2) {
        int2 e0 = __ldg(&g_edge[e + 0]);
        int2 e1 = __ldg(&g_edge[e + 1]);
        uint32_t v0 = 0, v1 = 0;
        if (act) {
            v0 = __ldg(&h[(size_t)e0.x * 20 + lane]);
            v1 = __ldg(&h[(size_t)e1.x * 20 + lane]);
        }
        float w0 = __int_as_float(e0.y), w1 = __int_as_float(e1.y);
        float2 f0 = __half22float2(*(const __half2*)&v0);
        float2 f1 = __half22float2(*(const __half2*)&v1);
        acc.x += w0 * f0.x + w1 * f1.x;
        acc.y += w0 * f0.y + w1 * f1.y;
    }
    if (e < end) {
        int2 ed = __ldg(&g_edge[e]);
        uint32_t v0 = 0;
        if (act) v0 = __ldg(&h[(size_t)ed.x * 20 + lane]);
        float w0 = __int_as_float(ed.y);
        float2 f0 = __half22float2(*(const __half2*)&v0);
        acc.x += w0 * f0.x;
        acc.y += w0 * f0.y;
    }
    if (act) {
        float2 b = *(const float2*)(bias + lane * 2);
        acc.x += b.x;
        acc.y += b.y;
    }

    float m = act ? fmaxf(acc.x, acc.y) : -INFINITY;
#pragma unroll
    for (int off = 16; off > 0; off >>= 1)
        m = fmaxf(m, __shfl_xor_sync(0xFFFFFFFF, m, off));
    float s = act ? (expf(acc.x - m) + expf(acc.y - m)) : 0.0f;
#pragma unroll
    for (int off = 16; off > 0; off >>= 1)
        s += __shfl_xor_sync(0xFFFFFFFF, s, off);
    float lse = logf(s);
    if (act) {
        *(float2*)(out + (size_t)node * OUTCH + lane * 2) =
            make_float2(acc.x - m - lse, acc.y - m - lse);
    }
}

// ------------------------- launch -------------------------

extern "C" void kernel_launch(void* const* d_in, const int* in_sizes, int n_in,
                              void* d_out, int out_size)
{
    const float* x  = (const float*)d_in[0];
    const int*   ei = (const int*)d_in[1];       // int32
    const float* W1 = (const float*)d_in[2];
    const float* b1 = (const float*)d_in[3];
    const float* W2 = (const float*)d_in[4];
    const float* b2 = (const float*)d_in[5];
    const float* W3 = (const float*)d_in[6];
    const float* b3 = (const float*)d_in[7];
    float* out = (float*)d_out;

    const int N = in_sizes[0] / CH;       // 100000
    const int E = in_sizes[1] / 2;        // 1600000
    const int NB = (N + SCAN_CHUNK - 1) / SCAN_CHUNK;

    // one-time stream/event setup (no device memory)
    static cudaStream_t s2 = nullptr;
    static cudaEvent_t evFork = nullptr, evG1 = nullptr;
    static cudaEvent_t evA1a = nullptr, evA1b = nullptr, evG2 = nullptr;
    static cudaEvent_t evA2a = nullptr, evA2b = nullptr, evG3 = nullptr;
    if (s2 == nullptr) {
        cudaStreamCreateWithFlags(&s2, cudaStreamNonBlocking);
        cudaEventCreateWithFlags(&evFork, cudaEventDisableTiming);
        cudaEventCreateWithFlags(&evG1, cudaEventDisableTiming);
        cudaEventCreateWithFlags(&evA1a, cudaEventDisableTiming);
        cudaEventCreateWithFlags(&evA1b, cudaEventDisableTiming);
        cudaEventCreateWithFlags(&evG2, cudaEventDisableTiming);
        cudaEventCreateWithFlags(&evA2a, cudaEventDisableTiming);
        cudaEventCreateWithFlags(&evA2b, cudaEventDisableTiming);
        cudaEventCreateWithFlags(&evG3, cudaEventDisableTiming);
    }

    const int mBlocks = (N + 127) / 128;          // 782
    const int mHalf   = (mBlocks + 1) / 2;        // 391 -> 50048 rows
    const int nodeSplit = mHalf * 128;            // 50048
    const int aggB0 = (nodeSplit + 7) / 8;                 // 6256
    const int aggB1 = (N - nodeSplit + 7) / 8;             // 6244

    // --- fork: convert_w + GEMM1 (full) on s2 ; CSR chain on capture stream --
    cudaEventRecord(evFork, 0);
    cudaStreamWaitEvent(s2, evFork, 0);
    convert_w_kernel<<<256, 256, 0, s2>>>(W1, W2, W3);
    {
        dim3 grid(2, mBlocks);
        gemm_h16_kernel<128, 0, 0, 0><<<grid, 256, 0, s2>>>(x, N, CH, CH, 0);  // x -> hA
    }
    cudaEventRecord(evG1, s2);

    zero_cnt_kernel<<<(N + 255) / 256, 256>>>(N);
    hist_kernel<<<(E + 255) / 256, 256>>>(ei, E);
    scan_partial_kernel<<<NB, 256>>>(N);
    scan_blocks_kernel<<<1, 128>>>(NB);
    scan_emit_kernel<<<NB, 256>>>(N, E);
    scatter_kernel<<<(E + 255) / 256, 256>>>(ei, E);

    // --- agg1 (hA -> agg), chunked; GEMM2 chunks overlap on s2 (agg -> hB) ---
    cudaStreamWaitEvent(0, evG1, 0);
    aggregate256_kernel<0, true><<<aggB0, 256>>>(b1, 0, N);
    cudaEventRecord(evA1a, 0);
    aggregate256_kernel<0, true><<<aggB1, 256>>>(b1, nodeSplit, N);
    cudaEventRecord(evA1b, 0);

    cudaStreamWaitEvent(s2, evA1a, 0);
    {
        dim3 grid(2, mHalf);
        gemm_h16_kernel<128, 1, 1, 1><<<grid, 256, 0, s2>>>(nullptr, N, CH, CH, 0);
    }
    cudaStreamWaitEvent(s2, evA1b, 0);
    {
        dim3 grid(2, mBlocks - mHalf);
        gemm_h16_kernel<128, 1, 1, 1><<<grid, 256, 0, s2>>>(nullptr, N, CH, CH, mHalf);
    }
    cudaEventRecord(evG2, s2);

    // --- agg2 (hB -> agg), chunked; GEMM3 chunks overlap on s2 (agg -> hA) ---
    cudaStreamWaitEvent(0, evG2, 0);
    aggregate256_kernel<1, true><<<aggB0, 256>>>(b2, 0, N);
    cudaEventRecord(evA2a, 0);
    aggregate256_kernel<1, true><<<aggB1, 256>>>(b2, nodeSplit, N);
    cudaEventRecord(evA2b, 0);

    cudaStreamWaitEvent(s2, evA2a, 0);
    {
        dim3 grid(1, mHalf);
        gemm_h16_kernel<64, 1, 2, 0><<<grid, 256, 0, s2>>>(nullptr, N, OUTCH, OUTCH, 0);
    }
    cudaStreamWaitEvent(s2, evA2b, 0);
    {
        dim3 grid(1, mBlocks - mHalf);
        gemm_h16_kernel<64, 1, 2, 0><<<grid, 256, 0, s2>>>(nullptr, N, OUTCH, OUTCH, mHalf);
    }
    cudaEventRecord(evG3, s2);

    // --- fused layer-3 aggregation + log_softmax (reads hA) ---
    cudaStreamWaitEvent(0, evG3, 0);
    agg40_softmax_kernel<<<(N + 3) / 4, 128>>>(b3, out, N);
}

// round 12
// speedup vs baseline: 1.0559x; 1.0559x over previous
#include <cuda_runtime.h>
#include <cuda_fp16.h>
#include <math.h>
#include <stdint.h>

// ---------------------------------------------------------------------------
// GCN (3-layer) on 100k nodes / 1.6M edges.  edge_index arrives int32.
// R12: h (gather source for 256-ch layers) stored fp8 e4m3 -> halves gather
// traffic; h+agg = 75MB fully L2-resident. R10 stream topology (R11 chunking
// reverted); R11 warp-based agg40+softmax kept. Layer-3 h stays fp16.
// ---------------------------------------------------------------------------

#define CH 256
#define OUTCH 40
#define N_NODES_MAX 100000
#define N_EDGES_MAX 1600000
#define SCAN_CHUNK 1024

__device__ __align__(16) uint8_t g_h8[(size_t)N_NODES_MAX * CH];    // 25 MB (e4m3)
__device__ __align__(16) __half  g_h16[(size_t)N_NODES_MAX * OUTCH]; // 8 MB (layer-3)
__device__ __align__(16) __half  g_agg16[(size_t)N_NODES_MAX * CH]; // 50 MB
__device__ __align__(16) __half g_w1t[CH * CH];      // [n][k] transposed
__device__ __align__(16) __half g_w2t[CH * CH];
__device__ __align__(16) __half g_w3t[64 * CH];      // padded to 64 rows
__device__ int   g_cnt[N_NODES_MAX];
__device__ int   g_rowptr[N_NODES_MAX + 1];
__device__ int   g_wptr[N_NODES_MAX];
__device__ float g_dinv[N_NODES_MAX];
__device__ __align__(8) int2 g_edge[N_EDGES_MAX];    // (src, norm bits)
__device__ int   g_blocksum[128];
__device__ int   g_blockoff[128];

// ------------------------- CSR build -------------------------

__global__ void zero_cnt_kernel(int n) {
    int i = blockIdx.x * blockDim.x + threadIdx.x;
    if (i < n) g_cnt[i] = 0;
}
__global__ void hist_kernel(const int* __restrict__ ei, int E) {
    int e = blockIdx.x * blockDim.x + threadIdx.x;
    if (e < E) atomicAdd(&g_cnt[ei[E + e]], 1);
}
__global__ void scan_partial_kernel(int n) {
    __shared__ int warpsum[8];
    int base = blockIdx.x * SCAN_CHUNK + threadIdx.x * 4;
    int s = 0;
#pragma unroll
    for (int j = 0; j < 4; j++) { int i = base + j; if (i < n) s += g_cnt[i]; }
    int lane = threadIdx.x & 31, w = threadIdx.x >> 5;
#pragma unroll
    for (int off = 16; off > 0; off >>= 1) s += __shfl_xor_sync(0xFFFFFFFF, s, off);
    if (lane == 0) warpsum[w] = s;
    __syncthreads();
    if (threadIdx.x == 0) {
        int t = 0;
#pragma unroll
        for (int k = 0; k < 8; k++) t += warpsum[k];
        g_blocksum[blockIdx.x] = t;
    }
}
__global__ void scan_blocks_kernel(int nb) {
    int t = threadIdx.x;
    int v = (t < nb) ? g_blocksum[t] : 0;
    int orig = v;
    int lane = t & 31, w = t >> 5;
#pragma unroll
    for (int off = 1; off < 32; off <<= 1) {
        int u = __shfl_up_sync(0xFFFFFFFF, v, off);
        if (lane >= off) v += u;
    }
    __shared__ int ws[4];
    if (lane == 31) ws[w] = v;
    __syncthreads();
    int add = 0;
    for (int k = 0; k < w; k++) add += ws[k];
    if (t < nb) g_blockoff[t] = v + add - orig;
}
__global__ void scan_emit_kernel(int n, int E) {
    __shared__ int warpincl[8];
    int base = blockIdx.x * SCAN_CHUNK + threadIdx.x * 4;
    int c[4];
    int s = 0;
#pragma unroll
    for (int j = 0; j < 4; j++) {
        int i = base + j;
        c[j] = (i < n) ? g_cnt[i] : 0;
        s += c[j];
    }
    int lane = threadIdx.x & 31, w = threadIdx.x >> 5;
    int v = s;
#pragma unroll
    for (int off = 1; off < 32; off <<= 1) {
        int u = __shfl_up_sync(0xFFFFFFFF, v, off);
        if (lane >= off) v += u;
    }
    if (lane == 31) warpincl[w] = v;
    __syncthreads();
    int add = 0;
    for (int k = 0; k < w; k++) add += warpincl[k];
    int run = g_blockoff[blockIdx.x] + add + v - s;
#pragma unroll
    for (int j = 0; j < 4; j++) {
        int i = base + j;
        if (i < n) {
            g_rowptr[i] = run;
            g_wptr[i]   = run;
            g_dinv[i]   = rsqrtf((float)c[j] + 1.0f);
            run += c[j];
        }
    }
    if (blockIdx.x == 0 && threadIdx.x == 0) g_rowptr[n] = E;
}
__global__ void scatter_kernel(const int* __restrict__ ei, int E) {
    int e = blockIdx.x * blockDim.x + threadIdx.x;
    if (e < E) {
        int s = ei[e];
        int d = ei[E + e];
        int pos = atomicAdd(&g_wptr[d], 1);
        float norm = g_dinv[s] * g_dinv[d];
        g_edge[pos] = make_int2(s, __float_as_int(norm));
    }
}

// W1,W2 [k][n] fp32 -> [n][k] fp16; W3 [k][40] -> [64][k] fp16 (zero-padded)
__global__ void convert_w_kernel(const float* __restrict__ W1,
                                 const float* __restrict__ W2,
                                 const float* __restrict__ W3) {
    int n = blockIdx.x;
    int k = threadIdx.x;
    g_w1t[n * 256 + k] = __float2half_rn(__ldg(&W1[k * 256 + n]));
    g_w2t[n * 256 + k] = __float2half_rn(__ldg(&W2[k * 256 + n]));
    if (n < 64)
        g_w3t[n * 256 + k] = __float2half_rn(n < OUTCH ? __ldg(&W3[k * OUTCH + n]) : 0.f);
}

// ------------------------- fp8 helpers -------------------------

__device__ __forceinline__ uint16_t f32x2_to_e4m3x2(float lo, float hi) {
    uint16_t r;
    asm("cvt.rn.satfinite.e4m3x2.f32 %0, %1, %2;" : "=h"(r) : "f"(hi), "f"(lo));
    return r;
}
__device__ __forceinline__ void e4m3x2_to_f32x2(uint16_t v, float& lo, float& hi) {
    uint32_t h2;
    asm("cvt.rn.f16x2.e4m3x2 %0, %1;" : "=r"(h2) : "h"(v));
    float2 f = __half22float2(*(__half2*)&h2);
    lo = f.x; hi = f.y;
}

// ------------------- fp16 mma GEMM: C[M,*] = A[M,256] @ W^T -----------------
// BM=128, BN=128 or 64, BK=16. 8 warps 2(M)x4(N); warp tile 64 x BN/4.
// ASEL: 0 = fp32 x (param), 1 = fp16 g_agg16.  WSEL: 0/1/2.
// OUT8: 1 -> write e4m3 to g_h8 (stride 256); 0 -> fp16 to g_h16 (stride OUTCH).

#define HSTR 24

__device__ __forceinline__ uint32_t smem_cast(const void* p) {
    return (uint32_t)__cvta_generic_to_shared(p);
}

template <int BN, int ASEL, int WSEL, int OUT8>
__global__ __launch_bounds__(256, 2) void gemm_h16_kernel(
    const float* __restrict__ Xf, int M, int NOUT)
{
    const __half* Bt = (WSEL == 0) ? g_w1t : (WSEL == 1) ? g_w2t : g_w3t;
    constexpr int NTN = BN / 32;

    __shared__ __half As[2][128][HSTR];
    __shared__ __half Bs[2][BN][HSTR];
    constexpr uint32_t ABUF = 128 * HSTR * 2;
    constexpr uint32_t BBUF = BN * HSTR * 2;

    const int tid  = threadIdx.x;
    const int wid  = tid >> 5;
    const int lane = tid & 31;
    const int grp  = lane >> 2;
    const int tig  = lane & 3;
    const int wm   = wid & 1;
    const int wn   = wid >> 1;
    const int m0   = blockIdx.y * 128;
    const int n0   = blockIdx.x * BN;

    const int row = tid >> 1;
    const int kc  = tid & 1;

    const int lg   = lane >> 3;
    const int lr   = lane & 7;
    uint32_t aAddrBase = smem_cast(&As[0][wm * 64 + (lg & 1) * 8 + lr][(lg >> 1) * 8]);
    uint32_t bAddrBase = smem_cast(&Bs[0][wn * (BN / 4) + (lg >> 1) * 8 + lr][(lg & 1) * 8]);

    uint4 aH; float4 aF0, aF1; uint4 bG;
    auto loadG = [&](int k0) {
        int gm = m0 + row;
        if (ASEL == 0) {
            if (gm < M) {
                aF0 = __ldg((const float4*)(Xf + (size_t)gm * 256 + k0 + kc * 8));
                aF1 = __ldg((const float4*)(Xf + (size_t)gm * 256 + k0 + kc * 8 + 4));
            } else {
                aF0 = aF1 = make_float4(0.f, 0.f, 0.f, 0.f);
            }
        } else {
            aH = (gm < M) ? __ldg((const uint4*)(g_agg16 + (size_t)gm * 256 + k0 + kc * 8))
                          : make_uint4(0u, 0u, 0u, 0u);
        }
        if (BN == 128 || tid < BN * 2)
            bG = __ldg((const uint4*)(Bt + (size_t)(n0 + row) * 256 + k0 + kc * 8));
    };
    auto storeS = [&](int buf) {
        if (ASEL == 0) {
            uint4 v;
            __half2* p = (__half2*)&v;
            p[0] = __floats2half2_rn(aF0.x, aF0.y);
            p[1] = __floats2half2_rn(aF0.z, aF0.w);
            p[2] = __floats2half2_rn(aF1.x, aF1.y);
            p[3] = __floats2half2_rn(aF1.z, aF1.w);
            *(uint4*)&As[buf][row][kc * 8] = v;
        } else {
            *(uint4*)&As[buf][row][kc * 8] = aH;
        }
        if (BN == 128 || tid < BN * 2)
            *(uint4*)&Bs[buf][row][kc * 8] = bG;
    };

    float acc[4][NTN][4];
#pragma unroll
    for (int mt = 0; mt < 4; mt++)
#pragma unroll
        for (int nt = 0; nt < NTN; nt++)
#pragma unroll
            for (int r = 0; r < 4; r++) acc[mt][nt][r] = 0.0f;

    loadG(0);
    storeS(0);
    __syncthreads();

    const int NT = 256 / 16;
    for (int kt = 0; kt < NT; kt++) {
        const int cur = kt & 1;
        if (kt + 1 < NT) loadG((kt + 1) * 16);

        uint32_t aOff = aAddrBase + cur * ABUF;
        uint32_t bOff = bAddrBase + cur * BBUF;
        uint32_t af[4][4], bf[NTN][2];
#pragma unroll
        for (int mt = 0; mt < 4; mt++) {
            asm volatile(
                "ldmatrix.sync.aligned.m8n8.x4.shared.b16 {%0,%1,%2,%3}, [%4];"
                : "=r"(af[mt][0]), "=r"(af[mt][1]), "=r"(af[mt][2]), "=r"(af[mt][3])
                : "r"(aOff + mt * (16 * HSTR * 2)));
        }
#pragma unroll
        for (int p = 0; p < NTN / 2; p++) {
            asm volatile(
                "ldmatrix.sync.aligned.m8n8.x4.shared.b16 {%0,%1,%2,%3}, [%4];"
                : "=r"(bf[2 * p][0]), "=r"(bf[2 * p][1]),
                  "=r"(bf[2 * p + 1][0]), "=r"(bf[2 * p + 1][1])
                : "r"(bOff + p * (16 * HSTR * 2)));
        }
#pragma unroll
        for (int mt = 0; mt < 4; mt++)
#pragma unroll
            for (int nt = 0; nt < NTN; nt++) {
                asm volatile(
                    "mma.sync.aligned.m16n8k16.row.col.f32.f16.f16.f32 "
                    "{%0,%1,%2,%3}, {%4,%5,%6,%7}, {%8,%9}, {%0,%1,%2,%3};"
                    : "+f"(acc[mt][nt][0]), "+f"(acc[mt][nt][1]),
                      "+f"(acc[mt][nt][2]), "+f"(acc[mt][nt][3])
                    : "r"(af[mt][0]), "r"(af[mt][1]), "r"(af[mt][2]), "r"(af[mt][3]),
                      "r"(bf[nt][0]), "r"(bf[nt][1]));
            }
        if (kt + 1 < NT) storeS(cur ^ 1);
        __syncthreads();
    }

#pragma unroll
    for (int mt = 0; mt < 4; mt++) {
        int gm = m0 + wm * 64 + mt * 16 + grp;
#pragma unroll
        for (int nt = 0; nt < NTN; nt++) {
            int gn = n0 + wn * (BN / 4) + nt * 8 + tig * 2;
            if (OUT8) {
                if (gm < M)
                    *(uint16_t*)(g_h8 + (size_t)gm * 256 + gn) =
                        f32x2_to_e4m3x2(acc[mt][nt][0], acc[mt][nt][1]);
                if (gm + 8 < M)
                    *(uint16_t*)(g_h8 + (size_t)(gm + 8) * 256 + gn) =
                        f32x2_to_e4m3x2(acc[mt][nt][2], acc[mt][nt][3]);
            } else if (gn < NOUT) {
                if (gm < M)
                    *(__half2*)(g_h16 + (size_t)gm * OUTCH + gn) =
                        __floats2half2_rn(acc[mt][nt][0], acc[mt][nt][1]);
                if (gm + 8 < M)
                    *(__half2*)(g_h16 + (size_t)(gm + 8) * OUTCH + gn) =
                        __floats2half2_rn(acc[mt][nt][2], acc[mt][nt][3]);
            }
        }
    }
}

// ------------------- Aggregation 256-ch: fp8 h gather -> agg16 --------------
// 8 nodes/block, 32 threads/node; thread gathers uint2 = 8 e4m3 (8B);
// row = 256 B, warp covers it. Edge loop unrolled x4.
template <bool RELU>
__global__ __launch_bounds__(256) void aggregate256_kernel(
    const float* __restrict__ bias, int n)
{
    const int node = blockIdx.x * 8 + (threadIdx.x >> 5);
    const int c8   = threadIdx.x & 31;
    if (node >= n) return;
    const uint2* h = (const uint2*)g_h8;          // row = 32 uint2
    const int beg = g_rowptr[node];
    const int end = g_rowptr[node + 1];
    const float di = g_dinv[node];
    const float dii = di * di;

    float acc[8];
    {
        uint2 v = h[(size_t)node * 32 + c8];
        const uint16_t* p = (const uint16_t*)&v;
#pragma unroll
        for (int q = 0; q < 4; q++) {
            float lo, hi;
            e4m3x2_to_f32x2(p[q], lo, hi);
            acc[q * 2 + 0] = lo * dii;
            acc[q * 2 + 1] = hi * dii;
        }
    }

    int e = beg;
    for (; e + 4 <= end; e += 4) {
        int2 e0 = __ldg(&g_edge[e + 0]);
        int2 e1 = __ldg(&g_edge[e + 1]);
        int2 e2 = __ldg(&g_edge[e + 2]);
        int2 e3 = __ldg(&g_edge[e + 3]);
        uint2 v0 = __ldg(&h[(size_t)e0.x * 32 + c8]);
        uint2 v1 = __ldg(&h[(size_t)e1.x * 32 + c8]);
        uint2 v2 = __ldg(&h[(size_t)e2.x * 32 + c8]);
        uint2 v3 = __ldg(&h[(size_t)e3.x * 32 + c8]);
        float w0 = __int_as_float(e0.y), w1 = __int_as_float(e1.y);
        float w2 = __int_as_float(e2.y), w3 = __int_as_float(e3.y);
        const uint16_t* p0 = (const uint16_t*)&v0;
        const uint16_t* p1 = (const uint16_t*)&v1;
        const uint16_t* p2 = (const uint16_t*)&v2;
        const uint16_t* p3 = (const uint16_t*)&v3;
#pragma unroll
        for (int q = 0; q < 4; q++) {
            float l0, h0, l1, h1, l2, h2_, l3, h3;
            e4m3x2_to_f32x2(p0[q], l0, h0);
            e4m3x2_to_f32x2(p1[q], l1, h1);
            e4m3x2_to_f32x2(p2[q], l2, h2_);
            e4m3x2_to_f32x2(p3[q], l3, h3);
            acc[q * 2 + 0] += w0 * l0 + w1 * l1 + w2 * l2 + w3 * l3;
            acc[q * 2 + 1] += w0 * h0 + w1 * h1 + w2 * h2_ + w3 * h3;
        }
    }
    for (; e < end; e++) {
        int2 ed = __ldg(&g_edge[e]);
        uint2 v0 = __ldg(&h[(size_t)ed.x * 32 + c8]);
        float w0 = __int_as_float(ed.y);
        const uint16_t* p0 = (const uint16_t*)&v0;
#pragma unroll
        for (int q = 0; q < 4; q++) {
            float lo, hi;
            e4m3x2_to_f32x2(p0[q], lo, hi);
            acc[q * 2 + 0] += w0 * lo;
            acc[q * 2 + 1] += w0 * hi;
        }
    }

    float4 b0 = __ldg((const float4*)(bias + c8 * 8));
    float4 b1 = __ldg((const float4*)(bias + c8 * 8 + 4));
    acc[0] += b0.x; acc[1] += b0.y; acc[2] += b0.z; acc[3] += b0.w;
    acc[4] += b1.x; acc[5] += b1.y; acc[6] += b1.z; acc[7] += b1.w;
    if (RELU) {
#pragma unroll
        for (int q = 0; q < 8; q++) acc[q] = fmaxf(acc[q], 0.0f);
    }
    uint4 ov;
    __half2* op = (__half2*)&ov;
    op[0] = __floats2half2_rn(acc[0], acc[1]);
    op[1] = __floats2half2_rn(acc[2], acc[3]);
    op[2] = __floats2half2_rn(acc[4], acc[5]);
    op[3] = __floats2half2_rn(acc[6], acc[7]);
    __stcs((float4*)((uint4*)g_agg16 + (size_t)node * 32 + c8), *(float4*)&ov);
}

// ---------- fused layer-3 aggregation (40 ch, fp16 h) + log_softmax ---------
// warp per node (4 nodes / 128-thr block); lanes 0..19 own 2 channels each.

__global__ __launch_bounds__(128) void agg40_softmax_kernel(
    const float* __restrict__ bias, float* __restrict__ out, int n)
{
    const int node = blockIdx.x * 4 + (threadIdx.x >> 5);
    const int lane = threadIdx.x & 31;
    if (node >= n) return;
    const uint32_t* h = (const uint32_t*)g_h16;   // 20 u32 per 40-half row
    const bool act = lane < 20;

    const int beg = g_rowptr[node];
    const int end = g_rowptr[node + 1];
    const float di = g_dinv[node];
    const float dii = di * di;

    float2 acc = make_float2(0.f, 0.f);
    if (act) {
        uint32_t sv = __ldg(&h[(size_t)node * 20 + lane]);
        float2 f = __half22float2(*(const __half2*)&sv);
        acc.x = f.x * dii;
        acc.y = f.y * dii;
    }
    int e = beg;
    for (; e + 2 <= end; e += 2) {
        int2 e0 = __ldg(&g_edge[e + 0]);
        int2 e1 = __ldg(&g_edge[e + 1]);
        uint32_t v0 = 0, v1 = 0;
        if (act) {
            v0 = __ldg(&h[(size_t)e0.x * 20 + lane]);
            v1 = __ldg(&h[(size_t)e1.x * 20 + lane]);
        }
        float w0 = __int_as_float(e0.y), w1 = __int_as_float(e1.y);
        float2 f0 = __half22float2(*(const __half2*)&v0);
        float2 f1 = __half22float2(*(const __half2*)&v1);
        acc.x += w0 * f0.x + w1 * f1.x;
        acc.y += w0 * f0.y + w1 * f1.y;
    }
    if (e < end) {
        int2 ed = __ldg(&g_edge[e]);
        uint32_t v0 = 0;
        if (act) v0 = __ldg(&h[(size_t)ed.x * 20 + lane]);
        float w0 = __int_as_float(ed.y);
        float2 f0 = __half22float2(*(const __half2*)&v0);
        acc.x += w0 * f0.x;
        acc.y += w0 * f0.y;
    }
    if (act) {
        float2 b = *(const float2*)(bias + lane * 2);
        acc.x += b.x;
        acc.y += b.y;
    }

    float m = act ? fmaxf(acc.x, acc.y) : -INFINITY;
#pragma unroll
    for (int off = 16; off > 0; off >>= 1)
        m = fmaxf(m, __shfl_xor_sync(0xFFFFFFFF, m, off));
    float s = act ? (expf(acc.x - m) + expf(acc.y - m)) : 0.0f;
#pragma unroll
    for (int off = 16; off > 0; off >>= 1)
        s += __shfl_xor_sync(0xFFFFFFFF, s, off);
    float lse = logf(s);
    if (act) {
        *(float2*)(out + (size_t)node * OUTCH + lane * 2) =
            make_float2(acc.x - m - lse, acc.y - m - lse);
    }
}

// ------------------------- launch -------------------------

extern "C" void kernel_launch(void* const* d_in, const int* in_sizes, int n_in,
                              void* d_out, int out_size)
{
    const float* x  = (const float*)d_in[0];
    const int*   ei = (const int*)d_in[1];       // int32
    const float* W1 = (const float*)d_in[2];
    const float* b1 = (const float*)d_in[3];
    const float* W2 = (const float*)d_in[4];
    const float* b2 = (const float*)d_in[5];
    const float* W3 = (const float*)d_in[6];
    const float* b3 = (const float*)d_in[7];
    float* out = (float*)d_out;

    const int N = in_sizes[0] / CH;       // 100000
    const int E = in_sizes[1] / 2;        // 1600000
    const int NB = (N + SCAN_CHUNK - 1) / SCAN_CHUNK;

    // one-time stream/event setup (no device memory)
    static cudaStream_t s2 = nullptr;
    static cudaEvent_t evFork = nullptr, evGemm = nullptr;
    if (s2 == nullptr) {
        cudaStreamCreateWithFlags(&s2, cudaStreamNonBlocking);
        cudaEventCreateWithFlags(&evFork, cudaEventDisableTiming);
        cudaEventCreateWithFlags(&evGemm, cudaEventDisableTiming);
    }

    const int mBlocks   = (N + 127) / 128;         // 782
    const int aggBlocks = (N + 7) / 8;

    // --- fork: convert_w + GEMM1 on s2, CSR build on the capture stream ---
    cudaEventRecord(evFork, 0);
    cudaStreamWaitEvent(s2, evFork, 0);
    convert_w_kernel<<<256, 256, 0, s2>>>(W1, W2, W3);
    {
        dim3 grid(2, mBlocks);
        gemm_h16_kernel<128, 0, 0, 1><<<grid, 256, 0, s2>>>(x, N, CH);
    }
    cudaEventRecord(evGemm, s2);

    zero_cnt_kernel<<<(N + 255) / 256, 256>>>(N);
    hist_kernel<<<(E + 255) / 256, 256>>>(ei, E);
    scan_partial_kernel<<<NB, 256>>>(N);
    scan_blocks_kernel<<<1, 128>>>(NB);
    scan_emit_kernel<<<NB, 256>>>(N, E);
    scatter_kernel<<<(E + 255) / 256, 256>>>(ei, E);

    // --- join: aggregate1 needs both CSR and GEMM1 ---
    cudaStreamWaitEvent(0, evGemm, 0);
    aggregate256_kernel<true><<<aggBlocks, 256>>>(b1, N);

    // --- layer 2 ---
    {
        dim3 grid(2, mBlocks);
        gemm_h16_kernel<128, 1, 1, 1><<<grid, 256>>>(nullptr, N, CH);
        aggregate256_kernel<true><<<aggBlocks, 256>>>(b2, N);
    }
    // --- layer 3: fp16 MMA GEMM (BN=64, out 40, fp16 h) + fused agg/softmax
    {
        dim3 grid(1, mBlocks);
        gemm_h16_kernel<64, 1, 2, 0><<<grid, 256>>>(nullptr, N, OUTCH);
        agg40_softmax_kernel<<<(N + 3) / 4, 128>>>(b3, out, N);
    }
}

// round 13
// speedup vs baseline: 1.0707x; 1.0140x over previous
#include <cuda_runtime.h>
#include <cuda_fp16.h>
#include <math.h>
#include <stdint.h>

// ---------------------------------------------------------------------------
// GCN (3-layer) on 100k nodes / 1.6M edges.  edge_index arrives int32.
// R13: agg ALSO stored fp8 e4m3 (h8 25MB + agg8 25MB = 50MB inter-layer
// state, fully L2-resident). GEMM A-loader converts e4m3->f16 in smem-store.
// Layer-3 h stays fp16 (softmax-facing).
// ---------------------------------------------------------------------------

#define CH 256
#define OUTCH 40
#define N_NODES_MAX 100000
#define N_EDGES_MAX 1600000
#define SCAN_CHUNK 1024

__device__ __align__(16) uint8_t g_h8[(size_t)N_NODES_MAX * CH];     // 25 MB (e4m3)
__device__ __align__(16) uint8_t g_agg8[(size_t)N_NODES_MAX * CH];   // 25 MB (e4m3)
__device__ __align__(16) __half  g_h16[(size_t)N_NODES_MAX * OUTCH]; // 8 MB (layer-3)
__device__ __align__(16) __half g_w1t[CH * CH];      // [n][k] transposed
__device__ __align__(16) __half g_w2t[CH * CH];
__device__ __align__(16) __half g_w3t[64 * CH];      // padded to 64 rows
__device__ int   g_cnt[N_NODES_MAX];
__device__ int   g_rowptr[N_NODES_MAX + 1];
__device__ int   g_wptr[N_NODES_MAX];
__device__ float g_dinv[N_NODES_MAX];
__device__ __align__(8) int2 g_edge[N_EDGES_MAX];    // (src, norm bits)
__device__ int   g_blocksum[128];
__device__ int   g_blockoff[128];

// ------------------------- CSR build -------------------------

__global__ void zero_cnt_kernel(int n) {
    int i = blockIdx.x * blockDim.x + threadIdx.x;
    if (i < n) g_cnt[i] = 0;
}
__global__ void hist_kernel(const int* __restrict__ ei, int E) {
    int e = blockIdx.x * blockDim.x + threadIdx.x;
    if (e < E) atomicAdd(&g_cnt[ei[E + e]], 1);
}
__global__ void scan_partial_kernel(int n) {
    __shared__ int warpsum[8];
    int base = blockIdx.x * SCAN_CHUNK + threadIdx.x * 4;
    int s = 0;
#pragma unroll
    for (int j = 0; j < 4; j++) { int i = base + j; if (i < n) s += g_cnt[i]; }
    int lane = threadIdx.x & 31, w = threadIdx.x >> 5;
#pragma unroll
    for (int off = 16; off > 0; off >>= 1) s += __shfl_xor_sync(0xFFFFFFFF, s, off);
    if (lane == 0) warpsum[w] = s;
    __syncthreads();
    if (threadIdx.x == 0) {
        int t = 0;
#pragma unroll
        for (int k = 0; k < 8; k++) t += warpsum[k];
        g_blocksum[blockIdx.x] = t;
    }
}
__global__ void scan_blocks_kernel(int nb) {
    int t = threadIdx.x;
    int v = (t < nb) ? g_blocksum[t] : 0;
    int orig = v;
    int lane = t & 31, w = t >> 5;
#pragma unroll
    for (int off = 1; off < 32; off <<= 1) {
        int u = __shfl_up_sync(0xFFFFFFFF, v, off);
        if (lane >= off) v += u;
    }
    __shared__ int ws[4];
    if (lane == 31) ws[w] = v;
    __syncthreads();
    int add = 0;
    for (int k = 0; k < w; k++) add += ws[k];
    if (t < nb) g_blockoff[t] = v + add - orig;
}
__global__ void scan_emit_kernel(int n, int E) {
    __shared__ int warpincl[8];
    int base = blockIdx.x * SCAN_CHUNK + threadIdx.x * 4;
    int c[4];
    int s = 0;
#pragma unroll
    for (int j = 0; j < 4; j++) {
        int i = base + j;
        c[j] = (i < n) ? g_cnt[i] : 0;
        s += c[j];
    }
    int lane = threadIdx.x & 31, w = threadIdx.x >> 5;
    int v = s;
#pragma unroll
    for (int off = 1; off < 32; off <<= 1) {
        int u = __shfl_up_sync(0xFFFFFFFF, v, off);
        if (lane >= off) v += u;
    }
    if (lane == 31) warpincl[w] = v;
    __syncthreads();
    int add = 0;
    for (int k = 0; k < w; k++) add += warpincl[k];
    int run = g_blockoff[blockIdx.x] + add + v - s;
#pragma unroll
    for (int j = 0; j < 4; j++) {
        int i = base + j;
        if (i < n) {
            g_rowptr[i] = run;
            g_wptr[i]   = run;
            g_dinv[i]   = rsqrtf((float)c[j] + 1.0f);
            run += c[j];
        }
    }
    if (blockIdx.x == 0 && threadIdx.x == 0) g_rowptr[n] = E;
}
__global__ void scatter_kernel(const int* __restrict__ ei, int E) {
    int e = blockIdx.x * blockDim.x + threadIdx.x;
    if (e < E) {
        int s = ei[e];
        int d = ei[E + e];
        int pos = atomicAdd(&g_wptr[d], 1);
        float norm = g_dinv[s] * g_dinv[d];
        g_edge[pos] = make_int2(s, __float_as_int(norm));
    }
}

// W1,W2 [k][n] fp32 -> [n][k] fp16; W3 [k][40] -> [64][k] fp16 (zero-padded)
__global__ void convert_w_kernel(const float* __restrict__ W1,
                                 const float* __restrict__ W2,
                                 const float* __restrict__ W3) {
    int n = blockIdx.x;
    int k = threadIdx.x;
    g_w1t[n * 256 + k] = __float2half_rn(__ldg(&W1[k * 256 + n]));
    g_w2t[n * 256 + k] = __float2half_rn(__ldg(&W2[k * 256 + n]));
    if (n < 64)
        g_w3t[n * 256 + k] = __float2half_rn(n < OUTCH ? __ldg(&W3[k * OUTCH + n]) : 0.f);
}

// ------------------------- fp8 helpers -------------------------

__device__ __forceinline__ uint16_t f32x2_to_e4m3x2(float lo, float hi) {
    uint16_t r;
    asm("cvt.rn.satfinite.e4m3x2.f32 %0, %1, %2;" : "=h"(r) : "f"(hi), "f"(lo));
    return r;
}
__device__ __forceinline__ uint32_t e4m3x2_to_h2(uint16_t v) {
    uint32_t h2;
    asm("cvt.rn.f16x2.e4m3x2 %0, %1;" : "=r"(h2) : "h"(v));
    return h2;
}
__device__ __forceinline__ void e4m3x2_to_f32x2(uint16_t v, float& lo, float& hi) {
    uint32_t h2 = e4m3x2_to_h2(v);
    float2 f = __half22float2(*(__half2*)&h2);
    lo = f.x; hi = f.y;
}

// ------------------- fp16 mma GEMM: C[M,*] = A[M,256] @ W^T -----------------
// BM=128, BN=128 or 64, BK=16. 8 warps 2(M)x4(N); warp tile 64 x BN/4.
// ASEL: 0 = fp32 x (param), 1 = fp8 g_agg8.  WSEL: 0/1/2.
// OUT8: 1 -> e4m3 to g_h8 (stride 256); 0 -> fp16 to g_h16 (stride OUTCH).

#define HSTR 24

__device__ __forceinline__ uint32_t smem_cast(const void* p) {
    return (uint32_t)__cvta_generic_to_shared(p);
}

template <int BN, int ASEL, int WSEL, int OUT8>
__global__ __launch_bounds__(256, 2) void gemm_h16_kernel(
    const float* __restrict__ Xf, int M, int NOUT)
{
    const __half* Bt = (WSEL == 0) ? g_w1t : (WSEL == 1) ? g_w2t : g_w3t;
    constexpr int NTN = BN / 32;

    __shared__ __half As[2][128][HSTR];
    __shared__ __half Bs[2][BN][HSTR];
    constexpr uint32_t ABUF = 128 * HSTR * 2;
    constexpr uint32_t BBUF = BN * HSTR * 2;

    const int tid  = threadIdx.x;
    const int wid  = tid >> 5;
    const int lane = tid & 31;
    const int grp  = lane >> 2;
    const int tig  = lane & 3;
    const int wm   = wid & 1;
    const int wn   = wid >> 1;
    const int m0   = blockIdx.y * 128;
    const int n0   = blockIdx.x * BN;

    const int row = tid >> 1;
    const int kc  = tid & 1;

    const int lg   = lane >> 3;
    const int lr   = lane & 7;
    uint32_t aAddrBase = smem_cast(&As[0][wm * 64 + (lg & 1) * 8 + lr][(lg >> 1) * 8]);
    uint32_t bAddrBase = smem_cast(&Bs[0][wn * (BN / 4) + (lg >> 1) * 8 + lr][(lg & 1) * 8]);

    uint2 a8; float4 aF0, aF1; uint4 bG;
    auto loadG = [&](int k0) {
        int gm = m0 + row;
        if (ASEL == 0) {
            if (gm < M) {
                aF0 = __ldg((const float4*)(Xf + (size_t)gm * 256 + k0 + kc * 8));
                aF1 = __ldg((const float4*)(Xf + (size_t)gm * 256 + k0 + kc * 8 + 4));
            } else {
                aF0 = aF1 = make_float4(0.f, 0.f, 0.f, 0.f);
            }
        } else {
            a8 = (gm < M) ? __ldg((const uint2*)(g_agg8 + (size_t)gm * 256 + k0 + kc * 8))
                          : make_uint2(0u, 0u);     // e4m3 0x00 == 0.0
        }
        if (BN == 128 || tid < BN * 2)
            bG = __ldg((const uint4*)(Bt + (size_t)(n0 + row) * 256 + k0 + kc * 8));
    };
    auto storeS = [&](int buf) {
        uint4 v;
        if (ASEL == 0) {
            __half2* p = (__half2*)&v;
            p[0] = __floats2half2_rn(aF0.x, aF0.y);
            p[1] = __floats2half2_rn(aF0.z, aF0.w);
            p[2] = __floats2half2_rn(aF1.x, aF1.y);
            p[3] = __floats2half2_rn(aF1.z, aF1.w);
        } else {
            const uint16_t* p8 = (const uint16_t*)&a8;
            uint32_t* pv = (uint32_t*)&v;
#pragma unroll
            for (int q = 0; q < 4; q++) pv[q] = e4m3x2_to_h2(p8[q]);
        }
        *(uint4*)&As[buf][row][kc * 8] = v;
        if (BN == 128 || tid < BN * 2)
            *(uint4*)&Bs[buf][row][kc * 8] = bG;
    };

    float acc[4][NTN][4];
#pragma unroll
    for (int mt = 0; mt < 4; mt++)
#pragma unroll
        for (int nt = 0; nt < NTN; nt++)
#pragma unroll
            for (int r = 0; r < 4; r++) acc[mt][nt][r] = 0.0f;

    loadG(0);
    storeS(0);
    __syncthreads();

    const int NT = 256 / 16;
    for (int kt = 0; kt < NT; kt++) {
        const int cur = kt & 1;
        if (kt + 1 < NT) loadG((kt + 1) * 16);

        uint32_t aOff = aAddrBase + cur * ABUF;
        uint32_t bOff = bAddrBase + cur * BBUF;
        uint32_t af[4][4], bf[NTN][2];
#pragma unroll
        for (int mt = 0; mt < 4; mt++) {
            asm volatile(
                "ldmatrix.sync.aligned.m8n8.x4.shared.b16 {%0,%1,%2,%3}, [%4];"
                : "=r"(af[mt][0]), "=r"(af[mt][1]), "=r"(af[mt][2]), "=r"(af[mt][3])
                : "r"(aOff + mt * (16 * HSTR * 2)));
        }
#pragma unroll
        for (int p = 0; p < NTN / 2; p++) {
            asm volatile(
                "ldmatrix.sync.aligned.m8n8.x4.shared.b16 {%0,%1,%2,%3}, [%4];"
                : "=r"(bf[2 * p][0]), "=r"(bf[2 * p][1]),
                  "=r"(bf[2 * p + 1][0]), "=r"(bf[2 * p + 1][1])
                : "r"(bOff + p * (16 * HSTR * 2)));
        }
#pragma unroll
        for (int mt = 0; mt < 4; mt++)
#pragma unroll
            for (int nt = 0; nt < NTN; nt++) {
                asm volatile(
                    "mma.sync.aligned.m16n8k16.row.col.f32.f16.f16.f32 "
                    "{%0,%1,%2,%3}, {%4,%5,%6,%7}, {%8,%9}, {%0,%1,%2,%3};"
                    : "+f"(acc[mt][nt][0]), "+f"(acc[mt][nt][1]),
                      "+f"(acc[mt][nt][2]), "+f"(acc[mt][nt][3])
                    : "r"(af[mt][0]), "r"(af[mt][1]), "r"(af[mt][2]), "r"(af[mt][3]),
                      "r"(bf[nt][0]), "r"(bf[nt][1]));
            }
        if (kt + 1 < NT) storeS(cur ^ 1);
        __syncthreads();
    }

#pragma unroll
    for (int mt = 0; mt < 4; mt++) {
        int gm = m0 + wm * 64 + mt * 16 + grp;
#pragma unroll
        for (int nt = 0; nt < NTN; nt++) {
            int gn = n0 + wn * (BN / 4) + nt * 8 + tig * 2;
            if (OUT8) {
                if (gm < M)
                    *(uint16_t*)(g_h8 + (size_t)gm * 256 + gn) =
                        f32x2_to_e4m3x2(acc[mt][nt][0], acc[mt][nt][1]);
                if (gm + 8 < M)
                    *(uint16_t*)(g_h8 + (size_t)(gm + 8) * 256 + gn) =
                        f32x2_to_e4m3x2(acc[mt][nt][2], acc[mt][nt][3]);
            } else if (gn < NOUT) {
                if (gm < M)
                    *(__half2*)(g_h16 + (size_t)gm * OUTCH + gn) =
                        __floats2half2_rn(acc[mt][nt][0], acc[mt][nt][1]);
                if (gm + 8 < M)
                    *(__half2*)(g_h16 + (size_t)(gm + 8) * OUTCH + gn) =
                        __floats2half2_rn(acc[mt][nt][2], acc[mt][nt][3]);
            }
        }
    }
}

// ------------------- Aggregation 256-ch: fp8 h gather -> fp8 agg ------------
// 8 nodes/block, 32 threads/node; thread gathers uint2 = 8 e4m3 (8B).
template <bool RELU>
__global__ __launch_bounds__(256) void aggregate256_kernel(
    const float* __restrict__ bias, int n)
{
    const int node = blockIdx.x * 8 + (threadIdx.x >> 5);
    const int c8   = threadIdx.x & 31;
    if (node >= n) return;
    const uint2* h = (const uint2*)g_h8;          // row = 32 uint2
    const int beg = g_rowptr[node];
    const int end = g_rowptr[node + 1];
    const float di = g_dinv[node];
    const float dii = di * di;

    float acc[8];
    {
        uint2 v = h[(size_t)node * 32 + c8];
        const uint16_t* p = (const uint16_t*)&v;
#pragma unroll
        for (int q = 0; q < 4; q++) {
            float lo, hi;
            e4m3x2_to_f32x2(p[q], lo, hi);
            acc[q * 2 + 0] = lo * dii;
            acc[q * 2 + 1] = hi * dii;
        }
    }

    int e = beg;
    for (; e + 4 <= end; e += 4) {
        int2 e0 = __ldg(&g_edge[e + 0]);
        int2 e1 = __ldg(&g_edge[e + 1]);
        int2 e2 = __ldg(&g_edge[e + 2]);
        int2 e3 = __ldg(&g_edge[e + 3]);
        uint2 v0 = __ldg(&h[(size_t)e0.x * 32 + c8]);
        uint2 v1 = __ldg(&h[(size_t)e1.x * 32 + c8]);
        uint2 v2 = __ldg(&h[(size_t)e2.x * 32 + c8]);
        uint2 v3 = __ldg(&h[(size_t)e3.x * 32 + c8]);
        float w0 = __int_as_float(e0.y), w1 = __int_as_float(e1.y);
        float w2 = __int_as_float(e2.y), w3 = __int_as_float(e3.y);
        const uint16_t* p0 = (const uint16_t*)&v0;
        const uint16_t* p1 = (const uint16_t*)&v1;
        const uint16_t* p2 = (const uint16_t*)&v2;
        const uint16_t* p3 = (const uint16_t*)&v3;
#pragma unroll
        for (int q = 0; q < 4; q++) {
            float l0, h0, l1, h1, l2, h2_, l3, h3;
            e4m3x2_to_f32x2(p0[q], l0, h0);
            e4m3x2_to_f32x2(p1[q], l1, h1);
            e4m3x2_to_f32x2(p2[q], l2, h2_);
            e4m3x2_to_f32x2(p3[q], l3, h3);
            acc[q * 2 + 0] += w0 * l0 + w1 * l1 + w2 * l2 + w3 * l3;
            acc[q * 2 + 1] += w0 * h0 + w1 * h1 + w2 * h2_ + w3 * h3;
        }
    }
    for (; e < end; e++) {
        int2 ed = __ldg(&g_edge[e]);
        uint2 v0 = __ldg(&h[(size_t)ed.x * 32 + c8]);
        float w0 = __int_as_float(ed.y);
        const uint16_t* p0 = (const uint16_t*)&v0;
#pragma unroll
        for (int q = 0; q < 4; q++) {
            float lo, hi;
            e4m3x2_to_f32x2(p0[q], lo, hi);
            acc[q * 2 + 0] += w0 * lo;
            acc[q * 2 + 1] += w0 * hi;
        }
    }

    float4 b0 = __ldg((const float4*)(bias + c8 * 8));
    float4 b1 = __ldg((const float4*)(bias + c8 * 8 + 4));
    acc[0] += b0.x; acc[1] += b0.y; acc[2] += b0.z; acc[3] += b0.w;
    acc[4] += b1.x; acc[5] += b1.y; acc[6] += b1.z; acc[7] += b1.w;
    if (RELU) {
#pragma unroll
        for (int q = 0; q < 8; q++) acc[q] = fmaxf(acc[q], 0.0f);
    }
    // pack to 8 x e4m3 = uint2, streaming store
    uint2 ov;
    uint16_t* op = (uint16_t*)&ov;
    op[0] = f32x2_to_e4m3x2(acc[0], acc[1]);
    op[1] = f32x2_to_e4m3x2(acc[2], acc[3]);
    op[2] = f32x2_to_e4m3x2(acc[4], acc[5]);
    op[3] = f32x2_to_e4m3x2(acc[6], acc[7]);
    __stcs((uint2*)((uint2*)g_agg8 + (size_t)node * 32 + c8), ov);
}

// ---------- fused layer-3 aggregation (40 ch, fp16 h) + log_softmax ---------
// warp per node (4 nodes / 128-thr block); lanes 0..19 own 2 channels each.

__global__ __launch_bounds__(128) void agg40_softmax_kernel(
    const float* __restrict__ bias, float* __restrict__ out, int n)
{
    const int node = blockIdx.x * 4 + (threadIdx.x >> 5);
    const int lane = threadIdx.x & 31;
    if (node >= n) return;
    const uint32_t* h = (const uint32_t*)g_h16;   // 20 u32 per 40-half row
    const bool act = lane < 20;

    const int beg = g_rowptr[node];
    const int end = g_rowptr[node + 1];
    const float di = g_dinv[node];
    const float dii = di * di;

    float2 acc = make_float2(0.f, 0.f);
    if (act) {
        uint32_t sv = __ldg(&h[(size_t)node * 20 + lane]);
        float2 f = __half22float2(*(const __half2*)&sv);
        acc.x = f.x * dii;
        acc.y = f.y * dii;
    }
    int e = beg;
    for (; e + 2 <= end; e += 2) {
        int2 e0 = __ldg(&g_edge[e + 0]);
        int2 e1 = __ldg(&g_edge[e + 1]);
        uint32_t v0 = 0, v1 = 0;
        if (act) {
            v0 = __ldg(&h[(size_t)e0.x * 20 + lane]);
            v1 = __ldg(&h[(size_t)e1.x * 20 + lane]);
        }
        float w0 = __int_as_float(e0.y), w1 = __int_as_float(e1.y);
        float2 f0 = __half22float2(*(const __half2*)&v0);
        float2 f1 = __half22float2(*(const __half2*)&v1);
        acc.x += w0 * f0.x + w1 * f1.x;
        acc.y += w0 * f0.y + w1 * f1.y;
    }
    if (e < end) {
        int2 ed = __ldg(&g_edge[e]);
        uint32_t v0 = 0;
        if (act) v0 = __ldg(&h[(size_t)ed.x * 20 + lane]);
        float w0 = __int_as_float(ed.y);
        float2 f0 = __half22float2(*(const __half2*)&v0);
        acc.x += w0 * f0.x;
        acc.y += w0 * f0.y;
    }
    if (act) {
        float2 b = *(const float2*)(bias + lane * 2);
        acc.x += b.x;
        acc.y += b.y;
    }

    float m = act ? fmaxf(acc.x, acc.y) : -INFINITY;
#pragma unroll
    for (int off = 16; off > 0; off >>= 1)
        m = fmaxf(m, __shfl_xor_sync(0xFFFFFFFF, m, off));
    float s = act ? (expf(acc.x - m) + expf(acc.y - m)) : 0.0f;
#pragma unroll
    for (int off = 16; off > 0; off >>= 1)
        s += __shfl_xor_sync(0xFFFFFFFF, s, off);
    float lse = logf(s);
    if (act) {
        *(float2*)(out + (size_t)node * OUTCH + lane * 2) =
            make_float2(acc.x - m - lse, acc.y - m - lse);
    }
}

// ------------------------- launch -------------------------

extern "C" void kernel_launch(void* const* d_in, const int* in_sizes, int n_in,
                              void* d_out, int out_size)
{
    const float* x  = (const float*)d_in[0];
    const int*   ei = (const int*)d_in[1];       // int32
    const float* W1 = (const float*)d_in[2];
    const float* b1 = (const float*)d_in[3];
    const float* W2 = (const float*)d_in[4];
    const float* b2 = (const float*)d_in[5];
    const float* W3 = (const float*)d_in[6];
    const float* b3 = (const float*)d_in[7];
    float* out = (float*)d_out;

    const int N = in_sizes[0] / CH;       // 100000
    const int E = in_sizes[1] / 2;        // 1600000
    const int NB = (N + SCAN_CHUNK - 1) / SCAN_CHUNK;

    // one-time stream/event setup (no device memory)
    static cudaStream_t s2 = nullptr;
    static cudaEvent_t evFork = nullptr, evGemm = nullptr;
    if (s2 == nullptr) {
        cudaStreamCreateWithFlags(&s2, cudaStreamNonBlocking);
        cudaEventCreateWithFlags(&evFork, cudaEventDisableTiming);
        cudaEventCreateWithFlags(&evGemm, cudaEventDisableTiming);
    }

    const int mBlocks   = (N + 127) / 128;         // 782
    const int aggBlocks = (N + 7) / 8;

    // --- fork: convert_w + GEMM1 on s2, CSR build on the capture stream ---
    cudaEventRecord(evFork, 0);
    cudaStreamWaitEvent(s2, evFork, 0);
    convert_w_kernel<<<256, 256, 0, s2>>>(W1, W2, W3);
    {
        dim3 grid(2, mBlocks);
        gemm_h16_kernel<128, 0, 0, 1><<<grid, 256, 0, s2>>>(x, N, CH);
    }
    cudaEventRecord(evGemm, s2);

    zero_cnt_kernel<<<(N + 255) / 256, 256>>>(N);
    hist_kernel<<<(E + 255) / 256, 256>>>(ei, E);
    scan_partial_kernel<<<NB, 256>>>(N);
    scan_blocks_kernel<<<1, 128>>>(NB);
    scan_emit_kernel<<<NB, 256>>>(N, E);
    scatter_kernel<<<(E + 255) / 256, 256>>>(ei, E);

    // --- join: aggregate1 needs both CSR and GEMM1 ---
    cudaStreamWaitEvent(0, evGemm, 0);
    aggregate256_kernel<true><<<aggBlocks, 256>>>(b1, N);

    // --- layer 2 ---
    {
        dim3 grid(2, mBlocks);
        gemm_h16_kernel<128, 1, 1, 1><<<grid, 256>>>(nullptr, N, CH);
        aggregate256_kernel<true><<<aggBlocks, 256>>>(b2, N);
    }
    // --- layer 3: fp16 MMA GEMM (BN=64, out 40, fp16 h) + fused agg/softmax
    {
        dim3 grid(1, mBlocks);
        gemm_h16_kernel<64, 1, 2, 0><<<grid, 256>>>(nullptr, N, OUTCH);
        agg40_softmax_kernel<<<(N + 3) / 4, 128>>>(b3, out, N);
    }
}

// round 14
// speedup vs baseline: 1.1278x; 1.0534x over previous
#include <cuda_runtime.h>
#include <cuda_fp16.h>
#include <math.h>
#include <stdint.h>

// ---------------------------------------------------------------------------
// GCN (3-layer) on 100k nodes / 1.6M edges.  edge_index arrives int32.
// R14: aggregation accumulates in half2 (HFMA2), flushed to fp32 every 16
// edges -> ~60% ALU-issue cut in the two big aggregations. fp8 h+agg kept.
// ---------------------------------------------------------------------------

#define CH 256
#define OUTCH 40
#define N_NODES_MAX 100000
#define N_EDGES_MAX 1600000
#define SCAN_CHUNK 1024

__device__ __align__(16) uint8_t g_h8[(size_t)N_NODES_MAX * CH];     // 25 MB (e4m3)
__device__ __align__(16) uint8_t g_agg8[(size_t)N_NODES_MAX * CH];   // 25 MB (e4m3)
__device__ __align__(16) __half  g_h16[(size_t)N_NODES_MAX * OUTCH]; // 8 MB (layer-3)
__device__ __align__(16) __half g_w1t[CH * CH];      // [n][k] transposed
__device__ __align__(16) __half g_w2t[CH * CH];
__device__ __align__(16) __half g_w3t[64 * CH];      // padded to 64 rows
__device__ int   g_cnt[N_NODES_MAX];
__device__ int   g_rowptr[N_NODES_MAX + 1];
__device__ int   g_wptr[N_NODES_MAX];
__device__ float g_dinv[N_NODES_MAX];
__device__ __align__(8) int2 g_edge[N_EDGES_MAX];    // (src, norm bits)
__device__ int   g_blocksum[128];
__device__ int   g_blockoff[128];

// ------------------------- CSR build -------------------------

__global__ void zero_cnt_kernel(int n) {
    int i = blockIdx.x * blockDim.x + threadIdx.x;
    if (i < n) g_cnt[i] = 0;
}
__global__ void hist_kernel(const int* __restrict__ ei, int E) {
    int e = blockIdx.x * blockDim.x + threadIdx.x;
    if (e < E) atomicAdd(&g_cnt[ei[E + e]], 1);
}
__global__ void scan_partial_kernel(int n) {
    __shared__ int warpsum[8];
    int base = blockIdx.x * SCAN_CHUNK + threadIdx.x * 4;
    int s = 0;
#pragma unroll
    for (int j = 0; j < 4; j++) { int i = base + j; if (i < n) s += g_cnt[i]; }
    int lane = threadIdx.x & 31, w = threadIdx.x >> 5;
#pragma unroll
    for (int off = 16; off > 0; off >>= 1) s += __shfl_xor_sync(0xFFFFFFFF, s, off);
    if (lane == 0) warpsum[w] = s;
    __syncthreads();
    if (threadIdx.x == 0) {
        int t = 0;
#pragma unroll
        for (int k = 0; k < 8; k++) t += warpsum[k];
        g_blocksum[blockIdx.x] = t;
    }
}
__global__ void scan_blocks_kernel(int nb) {
    int t = threadIdx.x;
    int v = (t < nb) ? g_blocksum[t] : 0;
    int orig = v;
    int lane = t & 31, w = t >> 5;
#pragma unroll
    for (int off = 1; off < 32; off <<= 1) {
        int u = __shfl_up_sync(0xFFFFFFFF, v, off);
        if (lane >= off) v += u;
    }
    __shared__ int ws[4];
    if (lane == 31) ws[w] = v;
    __syncthreads();
    int add = 0;
    for (int k = 0; k < w; k++) add += ws[k];
    if (t < nb) g_blockoff[t] = v + add - orig;
}
__global__ void scan_emit_kernel(int n, int E) {
    __shared__ int warpincl[8];
    int base = blockIdx.x * SCAN_CHUNK + threadIdx.x * 4;
    int c[4];
    int s = 0;
#pragma unroll
    for (int j = 0; j < 4; j++) {
        int i = base + j;
        c[j] = (i < n) ? g_cnt[i] : 0;
        s += c[j];
    }
    int lane = threadIdx.x & 31, w = threadIdx.x >> 5;
    int v = s;
#pragma unroll
    for (int off = 1; off < 32; off <<= 1) {
        int u = __shfl_up_sync(0xFFFFFFFF, v, off);
        if (lane >= off) v += u;
    }
    if (lane == 31) warpincl[w] = v;
    __syncthreads();
    int add = 0;
    for (int k = 0; k < w; k++) add += warpincl[k];
    int run = g_blockoff[blockIdx.x] + add + v - s;
#pragma unroll
    for (int j = 0; j < 4; j++) {
        int i = base + j;
        if (i < n) {
            g_rowptr[i] = run;
            g_wptr[i]   = run;
            g_dinv[i]   = rsqrtf((float)c[j] + 1.0f);
            run += c[j];
        }
    }
    if (blockIdx.x == 0 && threadIdx.x == 0) g_rowptr[n] = E;
}
__global__ void scatter_kernel(const int* __restrict__ ei, int E) {
    int e = blockIdx.x * blockDim.x + threadIdx.x;
    if (e < E) {
        int s = ei[e];
        int d = ei[E + e];
        int pos = atomicAdd(&g_wptr[d], 1);
        float norm = g_dinv[s] * g_dinv[d];
        g_edge[pos] = make_int2(s, __float_as_int(norm));
    }
}

// W1,W2 [k][n] fp32 -> [n][k] fp16; W3 [k][40] -> [64][k] fp16 (zero-padded)
__global__ void convert_w_kernel(const float* __restrict__ W1,
                                 const float* __restrict__ W2,
                                 const float* __restrict__ W3) {
    int n = blockIdx.x;
    int k = threadIdx.x;
    g_w1t[n * 256 + k] = __float2half_rn(__ldg(&W1[k * 256 + n]));
    g_w2t[n * 256 + k] = __float2half_rn(__ldg(&W2[k * 256 + n]));
    if (n < 64)
        g_w3t[n * 256 + k] = __float2half_rn(n < OUTCH ? __ldg(&W3[k * OUTCH + n]) : 0.f);
}

// ------------------------- fp8 helpers -------------------------

__device__ __forceinline__ uint16_t f32x2_to_e4m3x2(float lo, float hi) {
    uint16_t r;
    asm("cvt.rn.satfinite.e4m3x2.f32 %0, %1, %2;" : "=h"(r) : "f"(hi), "f"(lo));
    return r;
}
__device__ __forceinline__ uint32_t e4m3x2_to_h2(uint16_t v) {
    uint32_t h2;
    asm("cvt.rn.f16x2.e4m3x2 %0, %1;" : "=r"(h2) : "h"(v));
    return h2;
}
__device__ __forceinline__ void e4m3x2_to_f32x2(uint16_t v, float& lo, float& hi) {
    uint32_t h2 = e4m3x2_to_h2(v);
    float2 f = __half22float2(*(__half2*)&h2);
    lo = f.x; hi = f.y;
}

// ------------------- fp16 mma GEMM: C[M,*] = A[M,256] @ W^T -----------------
// BM=128, BN=128 or 64, BK=16. 8 warps 2(M)x4(N); warp tile 64 x BN/4.
// ASEL: 0 = fp32 x (param), 1 = fp8 g_agg8.  WSEL: 0/1/2.
// OUT8: 1 -> e4m3 to g_h8 (stride 256); 0 -> fp16 to g_h16 (stride OUTCH).

#define HSTR 24

__device__ __forceinline__ uint32_t smem_cast(const void* p) {
    return (uint32_t)__cvta_generic_to_shared(p);
}

template <int BN, int ASEL, int WSEL, int OUT8>
__global__ __launch_bounds__(256, 2) void gemm_h16_kernel(
    const float* __restrict__ Xf, int M, int NOUT)
{
    const __half* Bt = (WSEL == 0) ? g_w1t : (WSEL == 1) ? g_w2t : g_w3t;
    constexpr int NTN = BN / 32;

    __shared__ __half As[2][128][HSTR];
    __shared__ __half Bs[2][BN][HSTR];
    constexpr uint32_t ABUF = 128 * HSTR * 2;
    constexpr uint32_t BBUF = BN * HSTR * 2;

    const int tid  = threadIdx.x;
    const int wid  = tid >> 5;
    const int lane = tid & 31;
    const int grp  = lane >> 2;
    const int tig  = lane & 3;
    const int wm   = wid & 1;
    const int wn   = wid >> 1;
    const int m0   = blockIdx.y * 128;
    const int n0   = blockIdx.x * BN;

    const int row = tid >> 1;
    const int kc  = tid & 1;

    const int lg   = lane >> 3;
    const int lr   = lane & 7;
    uint32_t aAddrBase = smem_cast(&As[0][wm * 64 + (lg & 1) * 8 + lr][(lg >> 1) * 8]);
    uint32_t bAddrBase = smem_cast(&Bs[0][wn * (BN / 4) + (lg >> 1) * 8 + lr][(lg & 1) * 8]);

    uint2 a8; float4 aF0, aF1; uint4 bG;
    auto loadG = [&](int k0) {
        int gm = m0 + row;
        if (ASEL == 0) {
            if (gm < M) {
                aF0 = __ldg((const float4*)(Xf + (size_t)gm * 256 + k0 + kc * 8));
                aF1 = __ldg((const float4*)(Xf + (size_t)gm * 256 + k0 + kc * 8 + 4));
            } else {
                aF0 = aF1 = make_float4(0.f, 0.f, 0.f, 0.f);
            }
        } else {
            a8 = (gm < M) ? __ldg((const uint2*)(g_agg8 + (size_t)gm * 256 + k0 + kc * 8))
                          : make_uint2(0u, 0u);     // e4m3 0x00 == 0.0
        }
        if (BN == 128 || tid < BN * 2)
            bG = __ldg((const uint4*)(Bt + (size_t)(n0 + row) * 256 + k0 + kc * 8));
    };
    auto storeS = [&](int buf) {
        uint4 v;
        if (ASEL == 0) {
            __half2* p = (__half2*)&v;
            p[0] = __floats2half2_rn(aF0.x, aF0.y);
            p[1] = __floats2half2_rn(aF0.z, aF0.w);
            p[2] = __floats2half2_rn(aF1.x, aF1.y);
            p[3] = __floats2half2_rn(aF1.z, aF1.w);
        } else {
            const uint16_t* p8 = (const uint16_t*)&a8;
            uint32_t* pv = (uint32_t*)&v;
#pragma unroll
            for (int q = 0; q < 4; q++) pv[q] = e4m3x2_to_h2(p8[q]);
        }
        *(uint4*)&As[buf][row][kc * 8] = v;
        if (BN == 128 || tid < BN * 2)
            *(uint4*)&Bs[buf][row][kc * 8] = bG;
    };

    float acc[4][NTN][4];
#pragma unroll
    for (int mt = 0; mt < 4; mt++)
#pragma unroll
        for (int nt = 0; nt < NTN; nt++)
#pragma unroll
            for (int r = 0; r < 4; r++) acc[mt][nt][r] = 0.0f;

    loadG(0);
    storeS(0);
    __syncthreads();

    const int NT = 256 / 16;
    for (int kt = 0; kt < NT; kt++) {
        const int cur = kt & 1;
        if (kt + 1 < NT) loadG((kt + 1) * 16);

        uint32_t aOff = aAddrBase + cur * ABUF;
        uint32_t bOff = bAddrBase + cur * BBUF;
        uint32_t af[4][4], bf[NTN][2];
#pragma unroll
        for (int mt = 0; mt < 4; mt++) {
            asm volatile(
                "ldmatrix.sync.aligned.m8n8.x4.shared.b16 {%0,%1,%2,%3}, [%4];"
                : "=r"(af[mt][0]), "=r"(af[mt][1]), "=r"(af[mt][2]), "=r"(af[mt][3])
                : "r"(aOff + mt * (16 * HSTR * 2)));
        }
#pragma unroll
        for (int p = 0; p < NTN / 2; p++) {
            asm volatile(
                "ldmatrix.sync.aligned.m8n8.x4.shared.b16 {%0,%1,%2,%3}, [%4];"
                : "=r"(bf[2 * p][0]), "=r"(bf[2 * p][1]),
                  "=r"(bf[2 * p + 1][0]), "=r"(bf[2 * p + 1][1])
                : "r"(bOff + p * (16 * HSTR * 2)));
        }
#pragma unroll
        for (int mt = 0; mt < 4; mt++)
#pragma unroll
            for (int nt = 0; nt < NTN; nt++) {
                asm volatile(
                    "mma.sync.aligned.m16n8k16.row.col.f32.f16.f16.f32 "
                    "{%0,%1,%2,%3}, {%4,%5,%6,%7}, {%8,%9}, {%0,%1,%2,%3};"
                    : "+f"(acc[mt][nt][0]), "+f"(acc[mt][nt][1]),
                      "+f"(acc[mt][nt][2]), "+f"(acc[mt][nt][3])
                    : "r"(af[mt][0]), "r"(af[mt][1]), "r"(af[mt][2]), "r"(af[mt][3]),
                      "r"(bf[nt][0]), "r"(bf[nt][1]));
            }
        if (kt + 1 < NT) storeS(cur ^ 1);
        __syncthreads();
    }

#pragma unroll
    for (int mt = 0; mt < 4; mt++) {
        int gm = m0 + wm * 64 + mt * 16 + grp;
#pragma unroll
        for (int nt = 0; nt < NTN; nt++) {
            int gn = n0 + wn * (BN / 4) + nt * 8 + tig * 2;
            if (OUT8) {
                if (gm < M)
                    *(uint16_t*)(g_h8 + (size_t)gm * 256 + gn) =
                        f32x2_to_e4m3x2(acc[mt][nt][0], acc[mt][nt][1]);
                if (gm + 8 < M)
                    *(uint16_t*)(g_h8 + (size_t)(gm + 8) * 256 + gn) =
                        f32x2_to_e4m3x2(acc[mt][nt][2], acc[mt][nt][3]);
            } else if (gn < NOUT) {
                if (gm < M)
                    *(__half2*)(g_h16 + (size_t)gm * OUTCH + gn) =
                        __floats2half2_rn(acc[mt][nt][0], acc[mt][nt][1]);
                if (gm + 8 < M)
                    *(__half2*)(g_h16 + (size_t)(gm + 8) * OUTCH + gn) =
                        __floats2half2_rn(acc[mt][nt][2], acc[mt][nt][3]);
            }
        }
    }
}

// ------------------- Aggregation 256-ch: fp8 h gather -> fp8 agg ------------
// 8 nodes/block, 32 threads/node. half2 (HFMA2) accumulation, fp32 flush
// every 16 edges (e4m3 max 448 * 16 = 7168 << fp16 max: no overflow).
template <bool RELU>
__global__ __launch_bounds__(256) void aggregate256_kernel(
    const float* __restrict__ bias, int n)
{
    const int node = blockIdx.x * 8 + (threadIdx.x >> 5);
    const int c8   = threadIdx.x & 31;
    if (node >= n) return;
    const uint2* h = (const uint2*)g_h8;          // row = 32 uint2
    const int beg = g_rowptr[node];
    const int end = g_rowptr[node + 1];
    const float di = g_dinv[node];
    const float dii = di * di;

    float acc[8];
    {
        uint2 v = h[(size_t)node * 32 + c8];
        const uint16_t* p = (const uint16_t*)&v;
#pragma unroll
        for (int q = 0; q < 4; q++) {
            float lo, hi;
            e4m3x2_to_f32x2(p[q], lo, hi);
            acc[q * 2 + 0] = lo * dii;
            acc[q * 2 + 1] = hi * dii;
        }
    }

    __half2 hacc[4];
#pragma unroll
    for (int q = 0; q < 4; q++) hacc[q] = __float2half2_rn(0.f);

    auto flush = [&]() {
#pragma unroll
        for (int q = 0; q < 4; q++) {
            float2 f = __half22float2(hacc[q]);
            acc[q * 2 + 0] += f.x;
            acc[q * 2 + 1] += f.y;
            hacc[q] = __float2half2_rn(0.f);
        }
    };

    int e = beg;
    int it = 0;
    for (; e + 4 <= end; e += 4) {
        int2 e0 = __ldg(&g_edge[e + 0]);
        int2 e1 = __ldg(&g_edge[e + 1]);
        int2 e2 = __ldg(&g_edge[e + 2]);
        int2 e3 = __ldg(&g_edge[e + 3]);
        uint2 v0 = __ldg(&h[(size_t)e0.x * 32 + c8]);
        uint2 v1 = __ldg(&h[(size_t)e1.x * 32 + c8]);
        uint2 v2 = __ldg(&h[(size_t)e2.x * 32 + c8]);
        uint2 v3 = __ldg(&h[(size_t)e3.x * 32 + c8]);
        __half2 w0 = __float2half2_rn(__int_as_float(e0.y));
        __half2 w1 = __float2half2_rn(__int_as_float(e1.y));
        __half2 w2 = __float2half2_rn(__int_as_float(e2.y));
        __half2 w3 = __float2half2_rn(__int_as_float(e3.y));
        const uint16_t* p0 = (const uint16_t*)&v0;
        const uint16_t* p1 = (const uint16_t*)&v1;
        const uint16_t* p2 = (const uint16_t*)&v2;
        const uint16_t* p3 = (const uint16_t*)&v3;
#pragma unroll
        for (int q = 0; q < 4; q++) {
            uint32_t u0 = e4m3x2_to_h2(p0[q]);
            uint32_t u1 = e4m3x2_to_h2(p1[q]);
            uint32_t u2 = e4m3x2_to_h2(p2[q]);
            uint32_t u3 = e4m3x2_to_h2(p3[q]);
            hacc[q] = __hfma2(w0, *(__half2*)&u0, hacc[q]);
            hacc[q] = __hfma2(w1, *(__half2*)&u1, hacc[q]);
            hacc[q] = __hfma2(w2, *(__half2*)&u2, hacc[q]);
            hacc[q] = __hfma2(w3, *(__half2*)&u3, hacc[q]);
        }
        if (++it == 4) { flush(); it = 0; }
    }
    for (; e < end; e++) {
        int2 ed = __ldg(&g_edge[e]);
        uint2 v0 = __ldg(&h[(size_t)ed.x * 32 + c8]);
        __half2 w0 = __float2half2_rn(__int_as_float(ed.y));
        const uint16_t* p0 = (const uint16_t*)&v0;
#pragma unroll
        for (int q = 0; q < 4; q++) {
            uint32_t u0 = e4m3x2_to_h2(p0[q]);
            hacc[q] = __hfma2(w0, *(__half2*)&u0, hacc[q]);
        }
    }
    flush();

    float4 b0 = __ldg((const float4*)(bias + c8 * 8));
    float4 b1 = __ldg((const float4*)(bias + c8 * 8 + 4));
    acc[0] += b0.x; acc[1] += b0.y; acc[2] += b0.z; acc[3] += b0.w;
    acc[4] += b1.x; acc[5] += b1.y; acc[6] += b1.z; acc[7] += b1.w;
    if (RELU) {
#pragma unroll
        for (int q = 0; q < 8; q++) acc[q] = fmaxf(acc[q], 0.0f);
    }
    // pack to 8 x e4m3 = uint2, streaming store
    uint2 ov;
    uint16_t* op = (uint16_t*)&ov;
    op[0] = f32x2_to_e4m3x2(acc[0], acc[1]);
    op[1] = f32x2_to_e4m3x2(acc[2], acc[3]);
    op[2] = f32x2_to_e4m3x2(acc[4], acc[5]);
    op[3] = f32x2_to_e4m3x2(acc[6], acc[7]);
    __stcs((uint2*)((uint2*)g_agg8 + (size_t)node * 32 + c8), ov);
}

// ---------- fused layer-3 aggregation (40 ch, fp16 h) + log_softmax ---------
// warp per node (4 nodes / 128-thr block); lanes 0..19 own 2 channels each.

__global__ __launch_bounds__(128) void agg40_softmax_kernel(
    const float* __restrict__ bias, float* __restrict__ out, int n)
{
    const int node = blockIdx.x * 4 + (threadIdx.x >> 5);
    const int lane = threadIdx.x & 31;
    if (node >= n) return;
    const uint32_t* h = (const uint32_t*)g_h16;   // 20 u32 per 40-half row
    const bool act = lane < 20;

    const int beg = g_rowptr[node];
    const int end = g_rowptr[node + 1];
    const float di = g_dinv[node];
    const float dii = di * di;

    float2 acc = make_float2(0.f, 0.f);
    if (act) {
        uint32_t sv = __ldg(&h[(size_t)node * 20 + lane]);
        float2 f = __half22float2(*(const __half2*)&sv);
        acc.x = f.x * dii;
        acc.y = f.y * dii;
    }
    int e = beg;
    for (; e + 2 <= end; e += 2) {
        int2 e0 = __ldg(&g_edge[e + 0]);
        int2 e1 = __ldg(&g_edge[e + 1]);
        uint32_t v0 = 0, v1 = 0;
        if (act) {
            v0 = __ldg(&h[(size_t)e0.x * 20 + lane]);
            v1 = __ldg(&h[(size_t)e1.x * 20 + lane]);
        }
        float w0 = __int_as_float(e0.y), w1 = __int_as_float(e1.y);
        float2 f0 = __half22float2(*(const __half2*)&v0);
        float2 f1 = __half22float2(*(const __half2*)&v1);
        acc.x += w0 * f0.x + w1 * f1.x;
        acc.y += w0 * f0.y + w1 * f1.y;
    }
    if (e < end) {
        int2 ed = __ldg(&g_edge[e]);
        uint32_t v0 = 0;
        if (act) v0 = __ldg(&h[(size_t)ed.x * 20 + lane]);
        float w0 = __int_as_float(ed.y);
        float2 f0 = __half22float2(*(const __half2*)&v0);
        acc.x += w0 * f0.x;
        acc.y += w0 * f0.y;
    }
    if (act) {
        float2 b = *(const float2*)(bias + lane * 2);
        acc.x += b.x;
        acc.y += b.y;
    }

    float m = act ? fmaxf(acc.x, acc.y) : -INFINITY;
#pragma unroll
    for (int off = 16; off > 0; off >>= 1)
        m = fmaxf(m, __shfl_xor_sync(0xFFFFFFFF, m, off));
    float s = act ? (expf(acc.x - m) + expf(acc.y - m)) : 0.0f;
#pragma unroll
    for (int off = 16; off > 0; off >>= 1)
        s += __shfl_xor_sync(0xFFFFFFFF, s, off);
    float lse = logf(s);
    if (act) {
        *(float2*)(out + (size_t)node * OUTCH + lane * 2) =
            make_float2(acc.x - m - lse, acc.y - m - lse);
    }
}

// ------------------------- launch -------------------------

extern "C" void kernel_launch(void* const* d_in, const int* in_sizes, int n_in,
                              void* d_out, int out_size)
{
    const float* x  = (const float*)d_in[0];
    const int*   ei = (const int*)d_in[1];       // int32
    const float* W1 = (const float*)d_in[2];
    const float* b1 = (const float*)d_in[3];
    const float* W2 = (const float*)d_in[4];
    const float* b2 = (const float*)d_in[5];
    const float* W3 = (const float*)d_in[6];
    const float* b3 = (const float*)d_in[7];
    float* out = (float*)d_out;

    const int N = in_sizes[0] / CH;       // 100000
    const int E = in_sizes[1] / 2;        // 1600000
    const int NB = (N + SCAN_CHUNK - 1) / SCAN_CHUNK;

    // one-time stream/event setup (no device memory)
    static cudaStream_t s2 = nullptr;
    static cudaEvent_t evFork = nullptr, evGemm = nullptr;
    if (s2 == nullptr) {
        cudaStreamCreateWithFlags(&s2, cudaStreamNonBlocking);
        cudaEventCreateWithFlags(&evFork, cudaEventDisableTiming);
        cudaEventCreateWithFlags(&evGemm, cudaEventDisableTiming);
    }

    const int mBlocks   = (N + 127) / 128;         // 782
    const int aggBlocks = (N + 7) / 8;

    // --- fork: convert_w + GEMM1 on s2, CSR build on the capture stream ---
    cudaEventRecord(evFork, 0);
    cudaStreamWaitEvent(s2, evFork, 0);
    convert_w_kernel<<<256, 256, 0, s2>>>(W1, W2, W3);
    {
        dim3 grid(2, mBlocks);
        gemm_h16_kernel<128, 0, 0, 1><<<grid, 256, 0, s2>>>(x, N, CH);
    }
    cudaEventRecord(evGemm, s2);

    zero_cnt_kernel<<<(N + 255) / 256, 256>>>(N);
    hist_kernel<<<(E + 255) / 256, 256>>>(ei, E);
    scan_partial_kernel<<<NB, 256>>>(N);
    scan_blocks_kernel<<<1, 128>>>(NB);
    scan_emit_kernel<<<NB, 256>>>(N, E);
    scatter_kernel<<<(E + 255) / 256, 256>>>(ei, E);

    // --- join: aggregate1 needs both CSR and GEMM1 ---
    cudaStreamWaitEvent(0, evGemm, 0);
    aggregate256_kernel<true><<<aggBlocks, 256>>>(b1, N);

    // --- layer 2 ---
    {
        dim3 grid(2, mBlocks);
        gemm_h16_kernel<128, 1, 1, 1><<<grid, 256>>>(nullptr, N, CH);
        aggregate256_kernel<true><<<aggBlocks, 256>>>(b2, N);
    }
    // --- layer 3: fp16 MMA GEMM (BN=64, out 40, fp16 h) + fused agg/softmax
    {
        dim3 grid(1, mBlocks);
        gemm_h16_kernel<64, 1, 2, 0><<<grid, 256>>>(nullptr, N, OUTCH);
        agg40_softmax_kernel<<<(N + 3) / 4, 128>>>(b3, out, N);
    }
}